// round 5
// baseline (speedup 1.0000x reference)
#include <cuda_runtime.h>

// PyramidDownSampling fused, z-streaming + shuffle x-conv.
// out = [ x copy (2x256^3) | d1 3^3 s2 (2x128^3) | d2 5^3 s4 (2x64^3) ]
// Separable Gaussian: 1D factors recovered exactly as axis marginals of the
// provided 3D kernels (outer-product construction => marginals = factors).
//
// Block: 18 warps (576 thr). Tile: y 16, x 64, z chunk 32 (34 input slices).
// Warp w owns row gy = y0-2+w. Per slice:
//   A: load row (float2/lane) -> copy STG -> x-conv via shuffles -> tiny STS
//   B: y-conv from conflict-free smem vectors, z-conv via rolling registers.

#define S   256
#define SS  (S*S)
#define TY  16
#define TX  64
#define ZC  32

__global__ __launch_bounds__(576, 1)
void pyramid_kernel(const float* __restrict__ x,
                    const float* __restrict__ k0,   // 27  (3x3x3)
                    const float* __restrict__ k1,   // 125 (5x5x5)
                    float* __restrict__ out)
{
    __shared__ float xr1s[2][18][32];   // x-reduced for d1, per row
    __shared__ float xr2s[2][17][20];   // x-reduced for d2 (stride 20: bank-clean)
    __shared__ float wsm[24];           // gz[0:3) gy[3:6) gx[6:9) hz[9:14) hy[14:19) hx[19:24)

    const int tid  = threadIdx.x;
    const int w    = tid >> 5;
    const int lane = tid & 31;
    const unsigned FULL = 0xffffffffu;

    // ---- exact 1D factors: axis marginals of the 3D kernels ----
    if (tid < 24) {
        float s = 0.f;
        if (tid < 9) {
            int axis = tid / 3, idx = tid % 3;
            for (int u = 0; u < 3; u++)
                for (int v = 0; v < 3; v++) {
                    int a, b, c;
                    if (axis == 0) { a = idx; b = u; c = v; }
                    else if (axis == 1) { a = u; b = idx; c = v; }
                    else { a = u; b = v; c = idx; }
                    s += k0[(a * 3 + b) * 3 + c];
                }
        } else {
            int q = tid - 9, axis = q / 5, idx = q % 5;
            for (int u = 0; u < 5; u++)
                for (int v = 0; v < 5; v++) {
                    int a, b, c;
                    if (axis == 0) { a = idx; b = u; c = v; }
                    else if (axis == 1) { a = u; b = idx; c = v; }
                    else { a = u; b = v; c = idx; }
                    s += k1[(a * 5 + b) * 5 + c];
                }
        }
        wsm[tid] = s;
    }
    __syncthreads();

    const int bxs = blockIdx.x * TX;
    const int y0  = blockIdx.y * TY;
    const int zb  = (blockIdx.z & 7) * ZC;
    const int n   = blockIdx.z >> 3;

    const float* xn   = x   + (size_t)n * S * SS;
    float*       outx = out + (size_t)n * S * SS;
    float*       out1 = out + (size_t)2 * S * SS + (size_t)n * 128 * 128 * 128;
    float*       out2 = out + (size_t)2 * S * SS + (size_t)2 * 128 * 128 * 128
                            + (size_t)n * 64 * 64 * 64;

    // phase-A weights in registers
    const float gxw0 = wsm[6],  gxw1 = wsm[7],  gxw2 = wsm[8];
    const float hxw0 = wsm[19], hxw1 = wsm[20], hxw2 = wsm[21],
                hxw3 = wsm[22], hxw4 = wsm[23];

    const int r  = w;                                  // row 0..17
    const int gy = min(max(y0 - 2 + r, 0), S - 1);
    const int gxl = bxs - 2 + 2 * lane;

    float acc1 = 0.f, acc2 = 0.f;

    for (int t = 0; t < 34; t++) {
        const int zs = zb - 2 + t;
        const int gz = max(zs, 0);                     // zs <= 255 always
        const float* rp = xn + (size_t)gz * SS + (size_t)gy * S;

        // ---- Phase A: load row, emit copy, x-conv via shuffles ----
        float v0, v1, w0 = 0.f, w1 = 0.f;
        if (gxl >= 0) {
            float2 t2 = *(const float2*)(rp + gxl);
            v0 = t2.x; v1 = t2.y;
        } else {                                       // only lane 0 at bxs==0
            v0 = rp[0]; v1 = rp[0];
        }
        if (lane == 0) {
            float2 t2 = *(const float2*)(rp + bxs + 62);
            w0 = t2.x; w1 = t2.y;
        }

        // copy (interior rows, interior z)
        if (t >= 2 && r >= 2) {
            float* op = outx + (size_t)zs * SS + (size_t)(y0 + r - 2) * S + bxs;
            if (lane > 0) __stcs((float2*)(op + 2 * lane - 2), make_float2(v0, v1));
            else          __stcs((float2*)(op + 62),           make_float2(w0, w1));
        }

        // x-conv d1: xr1[l] = g0*X[2l-1] + g1*X[2l] + g2*X[2l+1]
        float nv0 = __shfl_down_sync(FULL, v0, 1);
        float nv1 = __shfl_down_sync(FULL, v1, 1);
        float w0b = __shfl_sync(FULL, w0, 0);
        float w1b = __shfl_sync(FULL, w1, 0);
        if (lane == 31) { nv0 = w0b; nv1 = w1b; }
        xr1s[t & 1][r][lane] = gxw0 * v1 + gxw1 * nv0 + gxw2 * nv1;

        // x-conv d2: xr2[l2] = sum_c h_c * X[4*l2-2+c]
        float A = hxw0 * v0 + hxw1 * v1;
        float B = hxw2 * v0 + hxw3 * v1;
        int  l2i = lane & 15;
        float a  = __shfl_sync(FULL, A, 2 * l2i);
        float b  = __shfl_sync(FULL, B, 2 * l2i + 1);
        float cv = __shfl_sync(FULL, v0, (2 * l2i + 2) & 31);
        float xc = (l2i < 15) ? cv : w0b;
        if (lane < 16 && r < 17)
            xr2s[t & 1][r][lane] = a + b + hxw4 * xc;

        __syncthreads();

        // ---- Phase B: y-conv from smem, z-conv rolling in registers ----
        const int bufi = t & 1;
        if (w < 8) {
            float p = wsm[3] * xr1s[bufi][2 * w + 1][lane]
                    + wsm[4] * xr1s[bufi][2 * w + 2][lane]
                    + wsm[5] * xr1s[bufi][2 * w + 3][lane];
            if (t & 1) {
                acc1 += wsm[2] * p;                    // close od=(zs-1)/2
                if (t > 1) {
                    int od = (zs - 1) >> 1;
                    __stcs(out1 + ((size_t)od * 128 + (y0 >> 1) + w) * 128
                                + (bxs >> 1) + lane, acc1);
                }
                acc1 = wsm[0] * p;                     // open next od
            } else {
                acc1 += wsm[1] * p;
            }
        } else if (w < 10) {
            const int j2 = ((w - 8) << 1) | (lane >> 4);
            const int l2 = lane & 15;
            const float* xb = &xr2s[bufi][4 * j2][0];
            float p = wsm[14] * xb[0 * 20 + l2]
                    + wsm[15] * xb[1 * 20 + l2]
                    + wsm[16] * xb[2 * 20 + l2]
                    + wsm[17] * xb[3 * 20 + l2]
                    + wsm[18] * xb[4 * 20 + l2];
            int ph = (zs + 2) & 3;
            if (ph == 0) {
                acc2 += wsm[13] * p;                   // close od2=(zs-2)/4
                if (t > 0) {
                    int od2 = (zs - 2) >> 2;
                    __stcs(out2 + ((size_t)od2 * 64 + (y0 >> 2) + j2) * 64
                                + (bxs >> 2) + l2, acc2);
                }
                acc2 = wsm[9] * p;                     // open next od2
            } else {
                acc2 += wsm[9 + ph] * p;
            }
        }
    }
}

extern "C" void kernel_launch(void* const* d_in, const int* in_sizes, int n_in,
                              void* d_out, int out_size)
{
    const float* x  = (const float*)d_in[0];
    const float* k0 = (const float*)d_in[1];
    const float* k1 = (const float*)d_in[2];
    float* out = (float*)d_out;

    dim3 grid(S / TX, S / TY, 8 * 2);   // (4, 16, 16)
    pyramid_kernel<<<grid, 576>>>(x, k0, k1, out);
}

// round 6
// speedup vs baseline: 2.2370x; 2.2370x over previous
#include <cuda_runtime.h>

// PyramidDownSampling fused: out = [ x copy (2x256^3) | d1 3^3 s2 (2x128^3) | d2 5^3 s4 (2x64^3) ]
// R6: tile-parallel (8192 blocks) + register/shuffle x-conv.
//   Phase A: 8 warps load the 10x10 (z,y) input rows of a 8x8x64 tile
//            (float2/lane), emit the copy straight from registers, reduce x
//            via warp shuffles, store tiny xr vectors to smem.
//   Phase B: d1 = 3x3 (z,y) taps of xr1 (conflict-free), d2 = 5x5 taps of xr2.

#define S  256
#define SS 65536
#define FULLM 0xffffffffu

__global__ __launch_bounds__(256)
void pyramid_kernel(const float* __restrict__ x,
                    const float* __restrict__ k0,   // 27  (3x3x3)
                    const float* __restrict__ k1,   // 125 (5x5x5)
                    float* __restrict__ out)
{
    __shared__ float xr1s[100][32];   // x-reduced for d1: rows r=dz*10+dy
    __shared__ float xr2s[100][20];   // x-reduced for d2 (pad 20: bank-clean)
    __shared__ float wsm[24];         // gz[0:3) gy[3:6) gx[6:9) hz[9:14) hy[14:19) hx[19:24)

    const int tid  = threadIdx.x;
    const int w    = tid >> 5;
    const int lane = tid & 31;

    // ---- exact 1D factors = axis marginals of the 3D kernels ----
    if (tid < 24) {
        float s = 0.f;
        if (tid < 9) {
            int axis = tid / 3, idx = tid % 3;
            for (int u = 0; u < 3; u++)
                for (int v = 0; v < 3; v++) {
                    int a, b, c;
                    if (axis == 0) { a = idx; b = u; c = v; }
                    else if (axis == 1) { a = u; b = idx; c = v; }
                    else { a = u; b = v; c = idx; }
                    s += k0[(a * 3 + b) * 3 + c];
                }
        } else {
            int q = tid - 9, axis = q / 5, idx = q % 5;
            for (int u = 0; u < 5; u++)
                for (int v = 0; v < 5; v++) {
                    int a, b, c;
                    if (axis == 0) { a = idx; b = u; c = v; }
                    else if (axis == 1) { a = u; b = idx; c = v; }
                    else { a = u; b = v; c = idx; }
                    s += k1[(a * 5 + b) * 5 + c];
                }
        }
        wsm[tid] = s;
    }
    __syncthreads();

    const int bxs = blockIdx.x * 64;
    const int y0  = blockIdx.y * 8;
    const int zc  = blockIdx.z & 31;
    const int n   = blockIdx.z >> 5;
    const int z0  = zc * 8;

    const float* xn   = x   + (size_t)n * S * SS;
    float*       outx = out + (size_t)n * S * SS;
    float*       out1 = out + (size_t)2 * S * SS + (size_t)n * 2097152;
    float*       out2 = out + (size_t)2 * S * SS + (size_t)2 * 2097152
                            + (size_t)n * 262144;

    const float gx0 = wsm[6],  gx1 = wsm[7],  gx2 = wsm[8];
    const float hx0 = wsm[19], hx1 = wsm[20], hx2 = wsm[21],
                hx3 = wsm[22], hx4 = wsm[23];

    const int  gxl  = bxs - 2 + 2 * lane;        // lane holds X[gxl], X[gxl+1]
    const int  xoff = max(gxl, 0);
    const bool fixl = (gxl < 0);                 // only bxs==0, lane==0
    const int  l2   = lane & 15;
    const int  coff = (lane == 0) ? bxs + 62 : gxl;   // copy-store offset

    // ---- Phase A: 100 input rows (dz 0..9, dy 0..9), strided over 8 warps ----
    #pragma unroll
    for (int k = 0; k < 13; k++) {
        const int r = w + 8 * k;
        if (r < 100) {
            const int dz = r / 10;
            const int dy = r - dz * 10;
            const int zs = z0 - 2 + dz;
            const int ys = y0 - 2 + dy;
            const int gz = min(max(zs, 0), S - 1);
            const int gy = min(max(ys, 0), S - 1);
            const float* rp = xn + ((size_t)gz << 16) + (gy << 8);

            float2 f2 = *(const float2*)(rp + xoff);
            float2 wv = *(const float2*)(rp + bxs + 62);   // X[62],X[63] rel (uniform)
            float v0 = f2.x;                               // X[2l-2]
            float v1 = fixl ? f2.x : f2.y;                 // X[2l-1]
            float w0 = wv.x, w1 = wv.y;

            // identity copy straight from registers (interior rows only)
            if (dz >= 2 && dy >= 2) {
                float* op = outx + ((size_t)zs << 16) + (ys << 8) + coff;
                float2 sv = (lane == 0) ? make_float2(w0, w1) : make_float2(v0, v1);
                __stcs((float2*)op, sv);
            }

            // x-conv for d1: xr1[l] = g0*X[2l-1] + g1*X[2l] + g2*X[2l+1]
            float nv0 = __shfl_down_sync(FULLM, v0, 1);
            float nv1 = __shfl_down_sync(FULLM, v1, 1);
            if (lane == 31) { nv0 = w0; nv1 = w1; }
            xr1s[r][lane] = gx0 * v1 + gx1 * nv0 + gx2 * nv1;

            // x-conv for d2: xr2[l2] = sum_c h_c * X[4*l2-2+c]
            float A = hx0 * v0 + hx1 * v1;
            float B = hx2 * v0 + hx3 * v1;
            float a = __shfl_sync(FULLM, A, 2 * l2);
            float b = __shfl_sync(FULLM, B, 2 * l2 + 1);
            float c = __shfl_sync(FULLM, v0, (2 * l2 + 2) & 31);
            float xc = (l2 == 15) ? w0 : c;
            if (lane < 16)
                xr2s[r][l2] = a + b + hx4 * xc;
        }
    }
    __syncthreads();

    // ---- Phase B: d1 = 3x3 (z,y) taps, conflict-free broadcast rows ----
    {
        const float gz0 = wsm[0], gz1 = wsm[1], gz2 = wsm[2];
        const float gy0 = wsm[3], gy1 = wsm[4], gy2 = wsm[5];
        #pragma unroll
        for (int q = 0; q < 2; q++) {
            const int t = tid + 256 * q;         // 512 outputs (4i x 4j x 32l)
            const int l = t & 31;
            const int j = (t >> 5) & 3;
            const int i = t >> 7;
            const int rb = (2 * i + 1) * 10 + (2 * j + 1);
            float acc;
            {
                float t0 = gy0 * xr1s[rb][l] + gy1 * xr1s[rb + 1][l] + gy2 * xr1s[rb + 2][l];
                acc = gz0 * t0;
            }
            {
                float t1 = gy0 * xr1s[rb + 10][l] + gy1 * xr1s[rb + 11][l] + gy2 * xr1s[rb + 12][l];
                acc += gz1 * t1;
            }
            {
                float t2 = gy0 * xr1s[rb + 20][l] + gy1 * xr1s[rb + 21][l] + gy2 * xr1s[rb + 22][l];
                acc += gz2 * t2;
            }
            const int od = (z0 >> 1) + i;
            const int oh = (y0 >> 1) + j;
            const int ow = (bxs >> 1) + l;
            __stcs(out1 + ((size_t)od * 128 + oh) * 128 + ow, acc);
        }
    }

    // ---- Phase B: d2 = 5x5 (z,y) taps (64 outputs: 2i x 2j x 16l) ----
    if (tid < 64) {
        const float hz0 = wsm[9],  hz1 = wsm[10], hz2 = wsm[11],
                    hz3 = wsm[12], hz4 = wsm[13];
        const float hy0 = wsm[14], hy1 = wsm[15], hy2 = wsm[16],
                    hy3 = wsm[17], hy4 = wsm[18];
        const int ll = tid & 15;
        const int j2 = (tid >> 4) & 1;
        const int i2 = tid >> 5;
        const int rb = (4 * i2) * 10 + 4 * j2;
        float acc = 0.f;
        const float hzw[5] = {hz0, hz1, hz2, hz3, hz4};
        #pragma unroll
        for (int a = 0; a < 5; a++) {
            const int ra = rb + 10 * a;
            float ty = hy0 * xr2s[ra][ll]     + hy1 * xr2s[ra + 1][ll]
                     + hy2 * xr2s[ra + 2][ll] + hy3 * xr2s[ra + 3][ll]
                     + hy4 * xr2s[ra + 4][ll];
            acc += hzw[a] * ty;
        }
        const int od2 = (z0 >> 2) + i2;
        const int oh2 = (y0 >> 2) + j2;
        const int ow2 = (bxs >> 2) + ll;
        __stcs(out2 + ((size_t)od2 * 64 + oh2) * 64 + ow2, acc);
    }
}

extern "C" void kernel_launch(void* const* d_in, const int* in_sizes, int n_in,
                              void* d_out, int out_size)
{
    const float* x  = (const float*)d_in[0];
    const float* k0 = (const float*)d_in[1];
    const float* k1 = (const float*)d_in[2];
    float* out = (float*)d_out;

    dim3 grid(S / 64, S / 8, 32 * 2);   // (4, 32, 64) = 8192 blocks
    pyramid_kernel<<<grid, 256>>>(x, k0, k1, out);
}

// round 7
// speedup vs baseline: 3.4090x; 1.5239x over previous
#include <cuda_runtime.h>

// PyramidDownSampling fused: out = [ x copy (2x256^3) | d1 3^3 s2 (2x128^3) | d2 5^3 s4 (2x64^3) ]
// R7: aligned float4 pipeline, TX=128.
//   Lane holds X[4l..4l+3]. Copy = direct STG.128. x-conv via 2 shfl_up
//   (left-neighbor v.z/v.w), lane0 patched from uniform left-halo float2.
//   No right halo needed (conv windows only extend left of aligned grid).

#define S  256
#define SS 65536
#define FULLM 0xffffffffu

__global__ __launch_bounds__(256)
void pyramid_kernel(const float* __restrict__ x,
                    const float* __restrict__ k0,   // 27  (3x3x3)
                    const float* __restrict__ k1,   // 125 (5x5x5)
                    float* __restrict__ out)
{
    __shared__ float xr1s[100][64];   // x-reduced for d1, rows r = dz*10+dy
    __shared__ float xr2s[100][32];   // x-reduced for d2
    __shared__ float wsm[24];         // gz[0:3) gy[3:6) gx[6:9) hz[9:14) hy[14:19) hx[19:24)

    const int tid  = threadIdx.x;
    const int w    = tid >> 5;
    const int lane = tid & 31;

    // ---- exact 1D factors = axis marginals of the 3D kernels ----
    if (tid < 24) {
        float s = 0.f;
        if (tid < 9) {
            int axis = tid / 3, idx = tid % 3;
            for (int u = 0; u < 3; u++)
                for (int v = 0; v < 3; v++) {
                    int a, b, c;
                    if (axis == 0) { a = idx; b = u; c = v; }
                    else if (axis == 1) { a = u; b = idx; c = v; }
                    else { a = u; b = v; c = idx; }
                    s += k0[(a * 3 + b) * 3 + c];
                }
        } else {
            int q = tid - 9, axis = q / 5, idx = q % 5;
            for (int u = 0; u < 5; u++)
                for (int v = 0; v < 5; v++) {
                    int a, b, c;
                    if (axis == 0) { a = idx; b = u; c = v; }
                    else if (axis == 1) { a = u; b = idx; c = v; }
                    else { a = u; b = v; c = idx; }
                    s += k1[(a * 5 + b) * 5 + c];
                }
        }
        wsm[tid] = s;
    }
    __syncthreads();

    const int bxs = blockIdx.x * 128;
    const int y0  = blockIdx.y * 8;
    const int zc  = blockIdx.z & 31;
    const int n   = blockIdx.z >> 5;
    const int z0  = zc * 8;

    const float* xn   = x   + (size_t)n * S * SS;
    float*       outx = out + (size_t)n * S * SS;
    float*       out1 = out + (size_t)2 * S * SS + (size_t)n * 2097152;
    float*       out2 = out + (size_t)2 * S * SS + (size_t)2 * 2097152
                            + (size_t)n * 262144;

    const float gxw0 = wsm[6],  gxw1 = wsm[7],  gxw2 = wsm[8];
    const float hxw0 = wsm[19], hxw1 = wsm[20], hxw2 = wsm[21],
                hxw3 = wsm[22], hxw4 = wsm[23];

    const int  gx    = bxs + 4 * lane;           // lane holds X[gx..gx+3]
    const bool bx0   = (bxs == 0);
    const int  hloff = bx0 ? 0 : bxs - 2;        // uniform left-halo float2

    // ---- Phase A: 100 input rows (dz 0..9, dy 0..9) over 8 warps ----
    #pragma unroll
    for (int k = 0; k < 13; k++) {
        const int r = w + 8 * k;
        if (r < 100) {
            const int dz = r / 10;
            const int dy = r - dz * 10;
            const int zs = z0 - 2 + dz;
            const int ys = y0 - 2 + dy;
            const int gz = min(max(zs, 0), S - 1);
            const int gy = min(max(ys, 0), S - 1);
            const float* rp = xn + ((size_t)gz << 16) + (gy << 8);

            const float4 v  = *(const float4*)(rp + gx);
            const float2 hl = *(const float2*)(rp + hloff);
            const float  e0 = hl.x;                       // X[bxs-2] (clamped)
            const float  e1 = bx0 ? hl.x : hl.y;          // X[bxs-1] (clamped)

            // identity copy straight from the load register
            if (dz >= 2 && dy >= 2)
                __stcs((float4*)(outx + ((size_t)zs << 16) + (ys << 8) + gx), v);

            // neighbor taps: X[4l-2], X[4l-1] = lane-1's v.z, v.w
            float p2 = __shfl_up_sync(FULLM, v.z, 1);
            float p3 = __shfl_up_sync(FULLM, v.w, 1);
            if (lane == 0) { p2 = e0; p3 = e1; }

            // d1: xr1[2l]   = g0*X[4l-1] + g1*X[4l]   + g2*X[4l+1]
            //     xr1[2l+1] = g0*X[4l+1] + g1*X[4l+2] + g2*X[4l+3]
            float2 o1;
            o1.x = gxw0 * p3  + gxw1 * v.x + gxw2 * v.y;
            o1.y = gxw0 * v.y + gxw1 * v.z + gxw2 * v.w;
            *(float2*)&xr1s[r][2 * lane] = o1;

            // d2: xr2[l] = h0*X[4l-2] + h1*X[4l-1] + h2*X[4l] + h3*X[4l+1] + h4*X[4l+2]
            xr2s[r][lane] = hxw0 * p2 + hxw1 * p3 + hxw2 * v.x
                          + hxw3 * v.y + hxw4 * v.z;
        }
    }
    __syncthreads();

    // ---- Phase B: d1 = 3x3 (z,y) taps -> 4i x 4j x 64l = 1024 outputs ----
    {
        const float gz0 = wsm[0], gz1 = wsm[1], gz2 = wsm[2];
        const float gy0 = wsm[3], gy1 = wsm[4], gy2 = wsm[5];
        #pragma unroll
        for (int q = 0; q < 4; q++) {
            const int t = tid + 256 * q;
            const int l = t & 63;
            const int j = (t >> 6) & 3;
            const int i = t >> 8;
            const int rb = (2 * i + 1) * 10 + (2 * j + 1);
            float acc =
                gz0 * (gy0 * xr1s[rb     ][l] + gy1 * xr1s[rb +  1][l] + gy2 * xr1s[rb +  2][l])
              + gz1 * (gy0 * xr1s[rb + 10][l] + gy1 * xr1s[rb + 11][l] + gy2 * xr1s[rb + 12][l])
              + gz2 * (gy0 * xr1s[rb + 20][l] + gy1 * xr1s[rb + 21][l] + gy2 * xr1s[rb + 22][l]);
            const int od = (z0 >> 1) + i;
            const int oh = (y0 >> 1) + j;
            const int ow = (bxs >> 1) + l;
            __stcs(out1 + ((size_t)od * 128 + oh) * 128 + ow, acc);
        }
    }

    // ---- Phase B: d2 = 5x5 (z,y) taps -> 2i x 2j x 32l = 128 outputs ----
    if (tid < 128) {
        const float hz0 = wsm[9],  hz1 = wsm[10], hz2 = wsm[11],
                    hz3 = wsm[12], hz4 = wsm[13];
        const float hy0 = wsm[14], hy1 = wsm[15], hy2 = wsm[16],
                    hy3 = wsm[17], hy4 = wsm[18];
        const int ll = tid & 31;
        const int j2 = (tid >> 5) & 1;
        const int i2 = tid >> 6;
        const int rb = (4 * i2) * 10 + 4 * j2;
        const float hzw[5] = {hz0, hz1, hz2, hz3, hz4};
        float acc = 0.f;
        #pragma unroll
        for (int a = 0; a < 5; a++) {
            const int ra = rb + 10 * a;
            float ty = hy0 * xr2s[ra][ll]     + hy1 * xr2s[ra + 1][ll]
                     + hy2 * xr2s[ra + 2][ll] + hy3 * xr2s[ra + 3][ll]
                     + hy4 * xr2s[ra + 4][ll];
            acc += hzw[a] * ty;
        }
        const int od2 = (z0 >> 2) + i2;
        const int oh2 = (y0 >> 2) + j2;
        const int ow2 = (bxs >> 2) + ll;
        __stcs(out2 + ((size_t)od2 * 64 + oh2) * 64 + ow2, acc);
    }
}

extern "C" void kernel_launch(void* const* d_in, const int* in_sizes, int n_in,
                              void* d_out, int out_size)
{
    const float* x  = (const float*)d_in[0];
    const float* k0 = (const float*)d_in[1];
    const float* k1 = (const float*)d_in[2];
    float* out = (float*)d_out;

    dim3 grid(S / 128, S / 8, 32 * 2);   // (2, 32, 64) = 4096 blocks
    pyramid_kernel<<<grid, 256>>>(x, k0, k1, out);
}